// round 9
// baseline (speedup 1.0000x reference)
#include <cuda_runtime.h>
#include <cstdint>

// LSM_IniReconNet fused two-stage GEMM, tf32 mma.sync.
//   stage 1: meas[128,256] = P[128,1024] @ Ws^T   (Ws [256,1024] row-major)
//   stage 2: Y[128,1024]   = meas @ Wi^T          (Wi [1024,256] row-major)
// K-slot permutation (k = 16*ks2 + 4*tc + 2*s + d): B fragments are coalesced
// LDG.128 (one per 8 MMAs); A tiles in smem keep conflict-free LDS.128 (one
// per 8 MMAs with the 4mf x 8nf warp tile) -> 1.0 L1-wavefront per MMA.
// 128 CTAs x 256 threads, 1 CTA/SM (176KB smem, full reg budget), one wave.

#define N_THREADS 256
#define N_CTA 128

#define MH_STRIDE 528            // % 32 == 16 -> conflict-free LDS.128
#define A_STRIDE  80             // % 32 == 16
#define A_BUF     (64 * A_STRIDE)            // 5120 floats / buffer
#define MH_OFF    0
#define A_OFF     (64 * MH_STRIDE)           // 33792
#define SMEM_FLOATS (A_OFF + 2 * A_BUF)      // 44032
#define SMEM_BYTES  (SMEM_FLOATS * 4)        // 176128

__device__ __forceinline__ uint32_t f2tf(float f) {
    uint32_t u;
    asm("cvt.rna.tf32.f32 %0, %1;" : "=r"(u) : "f"(f));
    return u;
}
__device__ __forceinline__ float tfv(float f) { return __uint_as_float(f2tf(f)); }

__device__ __forceinline__ void mma_tf32(float c[4], const uint32_t a[4],
                                         uint32_t b0, uint32_t b1) {
    asm volatile(
        "mma.sync.aligned.m16n8k8.row.col.f32.tf32.tf32.f32 "
        "{%0,%1,%2,%3}, {%4,%5,%6,%7}, {%8,%9}, {%0,%1,%2,%3};"
        : "+f"(c[0]), "+f"(c[1]), "+f"(c[2]), "+f"(c[3])
        : "r"(a[0]), "r"(a[1]), "r"(a[2]), "r"(a[3]), "r"(b0), "r"(b1));
}

__global__ void __launch_bounds__(N_THREADS, 1)
lsm_fused_kernel(const float* __restrict__ x, const float* __restrict__ ws,
                 const float* __restrict__ wi, float* __restrict__ y)
{
    extern __shared__ float sm[];
    float* MH = sm + MH_OFF;
    float* AB = sm + A_OFF;

    const int tid  = threadIdx.x;
    const int warp = tid >> 5;
    const int lane = tid & 31;
    const int g  = lane >> 2;
    const int tc = lane & 3;
    const int wm = warp >> 2;        // m-half: rows [wm*64, +64)
    const int wn = warp & 3;         // n-quarter: cols [wn*64, +64) per chunk
    const int p0 = blockIdx.x * 128;

    // ---- A loader precompute (permuted scatter): 4 float4 / thread / kc ----
    size_t a_goff[4]; int a_soff[4];
    #pragma unroll
    for (int i = 0; i < 4; ++i) {
        int v = tid + i * 256;
        int p = v >> 3, kq = v & 7;
        int gp = p0 + p;
        int b = gp >> 10, rem = gp & 1023, bh = rem >> 5, bw = rem & 31;
        a_goff[i] = ((size_t)b << 20) + (size_t)(bh << 5) * 1024 + (bw << 5) + (kq << 2);
        int grow = ((p >> 6) << 5) + (((p >> 4) & 3) << 3) + (p & 7);
        a_soff[i] = grow * A_STRIDE + 32 * (kq >> 2) + 4 * (kq & 3) + ((p >> 3) & 1);
    }

    // weight base pointers: row = wn*64 + nf*8 + g, inner 4*tc
    const float* wsp = ws + (size_t)(wn * 64 + g) * 1024 + (tc << 2);
    const float* wip = wi + (size_t)(wn * 64 + g) * 256 + (tc << 2);

    // ---- prologue: stage A(kc=0) ----
    #pragma unroll
    for (int i = 0; i < 4; ++i) {
        const float4 f = *reinterpret_cast<const float4*>(x + a_goff[i]);
        float* a = AB + a_soff[i];
        a[0] = tfv(f.x); a[2] = tfv(f.y); a[16] = tfv(f.z); a[18] = tfv(f.w);
    }
    __syncthreads();

    // ================= Stage 1 =================
    float acc[4][8][4];
    #pragma unroll
    for (int i = 0; i < 4; i++)
        #pragma unroll
        for (int j = 0; j < 8; j++)
            #pragma unroll
            for (int k = 0; k < 4; k++) acc[i][j][k] = 0.f;

    for (int kc = 0; kc < 32; ++kc) {
        float4 pf[4];
        const bool pre = (kc < 31);
        if (pre) {
            #pragma unroll
            for (int i = 0; i < 4; ++i)
                pf[i] = *reinterpret_cast<const float4*>(
                    x + a_goff[i] + (size_t)(kc + 1) * 1024);
        }

        const float* Ab = AB + (kc & 1) * A_BUF;
        const float* wk = wsp + (kc << 5);

        #pragma unroll
        for (int ks2 = 0; ks2 < 2; ++ks2) {
            uint32_t bb[8][4];
            #pragma unroll
            for (int nf = 0; nf < 8; ++nf) {
                const float4 f = *reinterpret_cast<const float4*>(
                    wk + nf * 8192 + ks2 * 16);
                bb[nf][0] = f2tf(f.x); bb[nf][1] = f2tf(f.y);
                bb[nf][2] = f2tf(f.z); bb[nf][3] = f2tf(f.w);
            }
            #pragma unroll
            for (int s = 0; s < 2; ++s) {
                const int ks = ks2 * 2 + s;
                #pragma unroll
                for (int mf = 0; mf < 4; ++mf) {
                    const float4 fa = *reinterpret_cast<const float4*>(
                        &Ab[(wm * 32 + mf * 8 + g) * A_STRIDE + (ks * 4 + tc) * 4]);
                    uint32_t a4[4] = {__float_as_uint(fa.x), __float_as_uint(fa.y),
                                      __float_as_uint(fa.z), __float_as_uint(fa.w)};
                    #pragma unroll
                    for (int nf = 0; nf < 8; ++nf)
                        mma_tf32(acc[mf][nf], a4, bb[nf][2 * s], bb[nf][2 * s + 1]);
                }
            }
        }

        if (pre) {
            float* Aw = AB + ((kc + 1) & 1) * A_BUF;
            #pragma unroll
            for (int i = 0; i < 4; ++i) {
                float* a = Aw + a_soff[i];
                a[0]  = tfv(pf[i].x); a[2]  = tfv(pf[i].y);
                a[16] = tfv(pf[i].z); a[18] = tfv(pf[i].w);
            }
        }
        __syncthreads();
    }

    // ---- dump meas to MH at permuted slot positions (STS.128 each) ----
    // value (row r = wm*64+mf*16+g(+8), col c = wn*64+nf*8+2tc+e):
    //   grow = wm*32+mf*8+g ; off = 128*wn + 32*((2nf+h)>>2) + 4*((2nf+h)&3)
    //                             + 16*(tc&1),  h = tc>>1 ; comps (e,r8)
    #pragma unroll
    for (int mf = 0; mf < 4; ++mf) {
        #pragma unroll
        for (int nf = 0; nf < 8; ++nf) {
            int t  = 2 * nf + (tc >> 1);
            int off = (wm * 32 + mf * 8 + g) * MH_STRIDE + 128 * wn
                    + 32 * (t >> 2) + 4 * (t & 3) + 16 * (tc & 1);
            float4 v;
            v.x = tfv(acc[mf][nf][0]);   // (r,   c)
            v.y = tfv(acc[mf][nf][2]);   // (r+8, c)
            v.z = tfv(acc[mf][nf][1]);   // (r,   c+1)
            v.w = tfv(acc[mf][nf][3]);   // (r+8, c+1)
            *reinterpret_cast<float4*>(MH + off) = v;
        }
    }
    __syncthreads();

    // ================= Stage 2 (no barriers) =================
    for (int nc = 0; nc < 4; ++nc) {
        float acc2[4][8][4];
        #pragma unroll
        for (int i = 0; i < 4; i++)
            #pragma unroll
            for (int j = 0; j < 8; j++)
                #pragma unroll
                for (int k = 0; k < 4; k++) acc2[i][j][k] = 0.f;

        const float* wn_ = wip + (size_t)nc * 65536;

        #pragma unroll 2
        for (int ks2 = 0; ks2 < 16; ++ks2) {
            uint32_t bb[8][4];
            #pragma unroll
            for (int nf = 0; nf < 8; ++nf) {
                const float4 f = *reinterpret_cast<const float4*>(
                    wn_ + nf * 2048 + ks2 * 16);
                bb[nf][0] = f2tf(f.x); bb[nf][1] = f2tf(f.y);
                bb[nf][2] = f2tf(f.z); bb[nf][3] = f2tf(f.w);
            }
            #pragma unroll
            for (int s = 0; s < 2; ++s) {
                const int ks = ks2 * 2 + s;
                #pragma unroll
                for (int mf = 0; mf < 4; ++mf) {
                    const float4 fa = *reinterpret_cast<const float4*>(
                        &MH[(wm * 32 + mf * 8 + g) * MH_STRIDE + (ks * 4 + tc) * 4]);
                    uint32_t a4[4] = {__float_as_uint(fa.x), __float_as_uint(fa.y),
                                      __float_as_uint(fa.z), __float_as_uint(fa.w)};
                    #pragma unroll
                    for (int nf = 0; nf < 8; ++nf)
                        mma_tf32(acc2[mf][nf], a4, bb[nf][2 * s], bb[nf][2 * s + 1]);
                }
            }
        }

        // epilogue: c = nc*256 + wn*64 + nf*8 + 2tc
        //   kh = nc*8 + wn*2 + (nf>>2), kw = (nf&3)*8 + 2tc
        #pragma unroll
        for (int mf = 0; mf < 4; ++mf) {
            #pragma unroll
            for (int half = 0; half < 2; ++half) {
                int r   = wm * 64 + mf * 16 + g + 8 * half;
                int gp  = p0 + r;
                int b   = gp >> 10;
                int rem = gp & 1023;
                int bh = rem >> 5, bw = rem & 31;
                float* yb = y + ((size_t)b << 20)
                              + (size_t)(bh << 5) * 1024 + (bw << 5);
                #pragma unroll
                for (int nf = 0; nf < 8; ++nf) {
                    int kh = nc * 8 + wn * 2 + (nf >> 2);
                    int kw = (nf & 3) * 8 + 2 * tc;
                    float2 v2;
                    v2.x = acc2[mf][nf][half * 2 + 0];
                    v2.y = acc2[mf][nf][half * 2 + 1];
                    *reinterpret_cast<float2*>(yb + (size_t)kh * 1024 + kw) = v2;
                }
            }
        }
    }
}

extern "C" void kernel_launch(void* const* d_in, const int* in_sizes, int n_in,
                              void* d_out, int out_size)
{
    const float* x  = (const float*)d_in[0];   // [16,1,1024,1024]
    const float* ws = (const float*)d_in[1];   // [256,1024]
    const float* wi = (const float*)d_in[2];   // [1024,256]
    float* y = (float*)d_out;                  // [16,1,1024,1024]

    cudaFuncSetAttribute(lsm_fused_kernel,
                         cudaFuncAttributeMaxDynamicSharedMemorySize, SMEM_BYTES);
    lsm_fused_kernel<<<N_CTA, N_THREADS, SMEM_BYTES>>>(x, ws, wi, y);
}

// round 11
// speedup vs baseline: 1.1458x; 1.1458x over previous
#include <cuda_runtime.h>
#include <cstdint>

// LSM_IniReconNet fused two-stage GEMM, tf32 mma.sync.
//   stage 1: meas[64,256] = P[64,1024] @ Ws^T   (Ws [256,1024] row-major)
//   stage 2: Y[64,1024]   = meas @ Wi^T         (Wi [1024,256] row-major)
// (4mf x 8nf) warp tile -> 1.0 L1-wavefront/MMA (A LDS.128 0.5 + B LDG.128
// 0.5, via the k-slot permutation k = 16*ks2 + 4*tc + 2*s + d).
// 128-thread CTAs, 64 patches each, 256 CTAs, 2 CTAs/SM: two independent
// barrier domains per SM so barrier/LDG stalls of one CTA hide under the
// other. Full per-thread register budget (64K regs / 256 threads = 256).

#define N_THREADS 128
#define N_CTA 256

#define MH_STRIDE 528            // % 32 == 16 -> conflict-free LDS.128
#define A_STRIDE  80             // % 32 == 16
#define A_BUF     (32 * A_STRIDE)            // 2560 floats / buffer
#define MH_OFF    0
#define A_OFF     (32 * MH_STRIDE)           // 16896
#define SMEM_FLOATS (A_OFF + 2 * A_BUF)      // 22016
#define SMEM_BYTES  (SMEM_FLOATS * 4)        // 88064 -> 2 CTAs/SM

__device__ __forceinline__ uint32_t f2tf(float f) {
    uint32_t u;
    asm("cvt.rna.tf32.f32 %0, %1;" : "=r"(u) : "f"(f));
    return u;
}
__device__ __forceinline__ float tfv(float f) { return __uint_as_float(f2tf(f)); }

__device__ __forceinline__ void mma_tf32(float c[4], const uint32_t a[4],
                                         uint32_t b0, uint32_t b1) {
    asm volatile(
        "mma.sync.aligned.m16n8k8.row.col.f32.tf32.tf32.f32 "
        "{%0,%1,%2,%3}, {%4,%5,%6,%7}, {%8,%9}, {%0,%1,%2,%3};"
        : "+f"(c[0]), "+f"(c[1]), "+f"(c[2]), "+f"(c[3])
        : "r"(a[0]), "r"(a[1]), "r"(a[2]), "r"(a[3]), "r"(b0), "r"(b1));
}

__global__ void __launch_bounds__(N_THREADS, 2)
lsm_fused_kernel(const float* __restrict__ x, const float* __restrict__ ws,
                 const float* __restrict__ wi, float* __restrict__ y)
{
    extern __shared__ float sm[];
    float* MH = sm + MH_OFF;
    float* AB = sm + A_OFF;

    const int tid  = threadIdx.x;
    const int w    = tid >> 5;       // warp 0..3: owns n-cols [w*64, +64)
    const int lane = tid & 31;
    const int g  = lane >> 2;
    const int tc = lane & 3;
    const int p0 = blockIdx.x * 64;

    // ---- A loader precompute (permuted scatter): 4 float4 / thread / kc ----
    size_t a_goff[4]; int a_soff[4];
    #pragma unroll
    for (int i = 0; i < 4; ++i) {
        int v = tid + i * 128;           // 0..511
        int p = v >> 3, kq = v & 7;      // p 0..63, kq 0..7
        int gp = p0 + p;
        int b = gp >> 10, rem = gp & 1023, bh = rem >> 5, bw = rem & 31;
        a_goff[i] = ((size_t)b << 20) + (size_t)(bh << 5) * 1024 + (bw << 5) + (kq << 2);
        int grow = (p >> 4) * 8 + (p & 7);   // 0..31 (pairs packed in comps)
        a_soff[i] = grow * A_STRIDE + 32 * (kq >> 2) + 4 * (kq & 3) + ((p >> 3) & 1);
    }

    // weight base pointers: row = w*64 + nf*8 + g, inner 4*tc
    const float* wsp = ws + (size_t)(w * 64 + g) * 1024 + (tc << 2);
    const float* wip = wi + (size_t)(w * 64 + g) * 256 + (tc << 2);

    // ---- prologue: stage A(kc=0) ----
    #pragma unroll
    for (int i = 0; i < 4; ++i) {
        const float4 f = *reinterpret_cast<const float4*>(x + a_goff[i]);
        float* a = AB + a_soff[i];
        a[0] = tfv(f.x); a[2] = tfv(f.y); a[16] = tfv(f.z); a[18] = tfv(f.w);
    }
    __syncthreads();

    // ================= Stage 1 =================
    float acc[4][8][4];
    #pragma unroll
    for (int i = 0; i < 4; i++)
        #pragma unroll
        for (int j = 0; j < 8; j++)
            #pragma unroll
            for (int k = 0; k < 4; k++) acc[i][j][k] = 0.f;

    for (int kc = 0; kc < 32; ++kc) {
        float4 pf[4];
        const bool pre = (kc < 31);
        if (pre) {
            #pragma unroll
            for (int i = 0; i < 4; ++i)
                pf[i] = *reinterpret_cast<const float4*>(
                    x + a_goff[i] + (size_t)(kc + 1) * 1024);
        }

        const float* Ab = AB + (kc & 1) * A_BUF;
        const float* wk = wsp + (kc << 5);

        #pragma unroll
        for (int ks2 = 0; ks2 < 2; ++ks2) {
            uint32_t bb[8][4];
            #pragma unroll
            for (int nf = 0; nf < 8; ++nf) {
                const float4 f = *reinterpret_cast<const float4*>(
                    wk + nf * 8192 + ks2 * 16);
                bb[nf][0] = f2tf(f.x); bb[nf][1] = f2tf(f.y);
                bb[nf][2] = f2tf(f.z); bb[nf][3] = f2tf(f.w);
            }
            #pragma unroll
            for (int s = 0; s < 2; ++s) {
                const int ks = ks2 * 2 + s;
                #pragma unroll
                for (int mf = 0; mf < 4; ++mf) {
                    const float4 fa = *reinterpret_cast<const float4*>(
                        &Ab[(mf * 8 + g) * A_STRIDE + (ks * 4 + tc) * 4]);
                    uint32_t a4[4] = {__float_as_uint(fa.x), __float_as_uint(fa.y),
                                      __float_as_uint(fa.z), __float_as_uint(fa.w)};
                    #pragma unroll
                    for (int nf = 0; nf < 8; ++nf)
                        mma_tf32(acc[mf][nf], a4, bb[nf][2 * s], bb[nf][2 * s + 1]);
                }
            }
        }

        if (pre) {
            float* Aw = AB + ((kc + 1) & 1) * A_BUF;
            #pragma unroll
            for (int i = 0; i < 4; ++i) {
                float* a = Aw + a_soff[i];
                a[0]  = tfv(pf[i].x); a[2]  = tfv(pf[i].y);
                a[16] = tfv(pf[i].z); a[18] = tfv(pf[i].w);
            }
        }
        __syncthreads();
    }

    // ---- dump meas to MH at permuted slot positions (STS.128 each) ----
    // col c = w*64 + nf*8 + 2tc + e ; quad q = 8*(4w + (nf>>1)) + 4*(tc&1)
    //   + 2*(nf&1) + (tc>>1) ; comps (x,y,z,w) = (c0, c2, c1, c3)
    #pragma unroll
    for (int mf = 0; mf < 4; ++mf) {
        #pragma unroll
        for (int nf = 0; nf < 8; ++nf) {
            int off = (mf * 8 + g) * MH_STRIDE
                    + 32 * (w * 4 + (nf >> 1)) + 16 * (tc & 1)
                    + 8 * (nf & 1) + 4 * (tc >> 1);
            float4 v;
            v.x = tfv(acc[mf][nf][0]);   // (r,   c)
            v.y = tfv(acc[mf][nf][2]);   // (r+8, c)
            v.z = tfv(acc[mf][nf][1]);   // (r,   c+1)
            v.w = tfv(acc[mf][nf][3]);   // (r+8, c+1)
            *reinterpret_cast<float4*>(MH + off) = v;
        }
    }
    __syncthreads();

    // ================= Stage 2 (no barriers) =================
    for (int nc = 0; nc < 4; ++nc) {
        float acc2[4][8][4];
        #pragma unroll
        for (int i = 0; i < 4; i++)
            #pragma unroll
            for (int j = 0; j < 8; j++)
                #pragma unroll
                for (int k = 0; k < 4; k++) acc2[i][j][k] = 0.f;

        const float* wn_ = wip + (size_t)nc * 65536;

        #pragma unroll 2
        for (int ks2 = 0; ks2 < 16; ++ks2) {
            uint32_t bb[8][4];
            #pragma unroll
            for (int nf = 0; nf < 8; ++nf) {
                const float4 f = *reinterpret_cast<const float4*>(
                    wn_ + nf * 2048 + ks2 * 16);
                bb[nf][0] = f2tf(f.x); bb[nf][1] = f2tf(f.y);
                bb[nf][2] = f2tf(f.z); bb[nf][3] = f2tf(f.w);
            }
            #pragma unroll
            for (int s = 0; s < 2; ++s) {
                const int ks = ks2 * 2 + s;
                #pragma unroll
                for (int mf = 0; mf < 4; ++mf) {
                    const float4 fa = *reinterpret_cast<const float4*>(
                        &MH[(mf * 8 + g) * MH_STRIDE + (ks * 4 + tc) * 4]);
                    uint32_t a4[4] = {__float_as_uint(fa.x), __float_as_uint(fa.y),
                                      __float_as_uint(fa.z), __float_as_uint(fa.w)};
                    #pragma unroll
                    for (int nf = 0; nf < 8; ++nf)
                        mma_tf32(acc2[mf][nf], a4, bb[nf][2 * s], bb[nf][2 * s + 1]);
                }
            }
        }

        // epilogue: c = nc*256 + w*64 + nf*8 + 2tc
        //   kh = nc*8 + w*2 + (nf>>2), kw = (nf&3)*8 + 2tc
        #pragma unroll
        for (int mf = 0; mf < 4; ++mf) {
            #pragma unroll
            for (int half = 0; half < 2; ++half) {
                int r   = mf * 16 + g + 8 * half;
                int gp  = p0 + r;
                int b   = gp >> 10;
                int rem = gp & 1023;
                int bh = rem >> 5, bw = rem & 31;
                float* yb = y + ((size_t)b << 20)
                              + (size_t)(bh << 5) * 1024 + (bw << 5);
                #pragma unroll
                for (int nf = 0; nf < 8; ++nf) {
                    int kh = nc * 8 + w * 2 + (nf >> 2);
                    int kw = (nf & 3) * 8 + 2 * tc;
                    float2 v2;
                    v2.x = acc2[mf][nf][half * 2 + 0];
                    v2.y = acc2[mf][nf][half * 2 + 1];
                    *reinterpret_cast<float2*>(yb + (size_t)kh * 1024 + kw) = v2;
                }
            }
        }
    }
}

extern "C" void kernel_launch(void* const* d_in, const int* in_sizes, int n_in,
                              void* d_out, int out_size)
{
    const float* x  = (const float*)d_in[0];   // [16,1,1024,1024]
    const float* ws = (const float*)d_in[1];   // [256,1024]
    const float* wi = (const float*)d_in[2];   // [1024,256]
    float* y = (float*)d_out;                  // [16,1,1024,1024]

    cudaFuncSetAttribute(lsm_fused_kernel,
                         cudaFuncAttributeMaxDynamicSharedMemorySize, SMEM_BYTES);
    lsm_fused_kernel<<<N_CTA, N_THREADS, SMEM_BYTES>>>(x, ws, wi, y);
}

// round 13
// speedup vs baseline: 1.2724x; 1.1106x over previous
#include <cuda_runtime.h>
#include <cstdint>

// LSM_IniReconNet fused two-stage GEMM, tf32 mma.sync.  (R7 + B pipelining)
//   stage 1: meas[64,256] = P[64,1024] @ Ws^T   (Ws [256,1024] row-major)
//   stage 2: Y[64,1024]   = meas @ Wi^T         (Wi [1024,256] row-major)
// K-slot permutation (k = 16*ks2 + 4*tc + 2*s + d): B fragments are coalesced
// LDG.128; A tiles in smem keep conflict-free LDS.128 fragments.
// NEW: register-level software pipeline on B — each ks2 block's 4 LDG.128s
// are issued one block ahead (and across kc barriers / nc chunks), hiding the
// ~240cyc L2 latency that R7 exposed. 256 CTAs x 256 thr, 2 CTAs/SM.

#define N_THREADS 256
#define N_CTA 256

#define MH_STRIDE 528            // % 32 == 16 -> conflict-free LDS.128
#define A_STRIDE  80             // % 32 == 16
#define A_BUF     (32 * A_STRIDE)
#define MH_OFF    0
#define A_OFF     (32 * MH_STRIDE)
#define SMEM_FLOATS (A_OFF + 2 * A_BUF)
#define SMEM_BYTES  (SMEM_FLOATS * 4)    // 88064

__device__ __forceinline__ uint32_t f2tf(float f) {
    uint32_t u;
    asm("cvt.rna.tf32.f32 %0, %1;" : "=r"(u) : "f"(f));
    return u;
}
__device__ __forceinline__ float tfv(float f) { return __uint_as_float(f2tf(f)); }

__device__ __forceinline__ void mma_tf32(float c[4], const uint32_t a[4],
                                         uint32_t b0, uint32_t b1) {
    asm volatile(
        "mma.sync.aligned.m16n8k8.row.col.f32.tf32.tf32.f32 "
        "{%0,%1,%2,%3}, {%4,%5,%6,%7}, {%8,%9}, {%0,%1,%2,%3};"
        : "+f"(c[0]), "+f"(c[1]), "+f"(c[2]), "+f"(c[3])
        : "r"(a[0]), "r"(a[1]), "r"(a[2]), "r"(a[3]), "r"(b0), "r"(b1));
}

__global__ void __launch_bounds__(N_THREADS, 2)
lsm_fused_kernel(const float* __restrict__ x, const float* __restrict__ ws,
                 const float* __restrict__ wi, float* __restrict__ y)
{
    extern __shared__ float sm[];
    float* MH = sm + MH_OFF;
    float* AB = sm + A_OFF;

    const int tid  = threadIdx.x;
    const int warp = tid >> 5;       // owns n-cols [warp*32, +32)
    const int lane = tid & 31;
    const int g  = lane >> 2;
    const int tc = lane & 3;
    const int p0 = blockIdx.x * 64;

    // ---- A loader precompute (permuted scatter): 2 float4 / thread / kc ----
    size_t a_goff[2]; int a_soff[2];
    #pragma unroll
    for (int i = 0; i < 2; ++i) {
        int v = tid + i * 256;
        int p = v >> 3, kq = v & 7;
        int gp = p0 + p;
        int b = gp >> 10, rem = gp & 1023, bh = rem >> 5, bw = rem & 31;
        a_goff[i] = ((size_t)b << 20) + (size_t)(bh << 5) * 1024 + (bw << 5) + (kq << 2);
        a_soff[i] = ((p >> 4) * 8 + (p & 7)) * A_STRIDE
                    + 32 * (kq >> 2) + 4 * (kq & 3) + ((p >> 3) & 1);
    }

    // weight base pointers: row = warp*32 + nf*8 + g, inner offset 4*tc
    const float* wsp = ws + (size_t)(warp * 32 + g) * 1024 + (tc << 2);
    const float* wip = wi + (size_t)(warp * 32 + g) * 256 + (tc << 2);

    // ---- prologue: stage A(kc=0); preload B(kc=0, ks2=0) ----
    float4 Bf[4];
    #pragma unroll
    for (int nf = 0; nf < 4; ++nf)
        Bf[nf] = *reinterpret_cast<const float4*>(wsp + nf * 8192);
    #pragma unroll
    for (int i = 0; i < 2; ++i) {
        const float4 f = *reinterpret_cast<const float4*>(x + a_goff[i]);
        float* a = AB + a_soff[i];
        a[0] = tfv(f.x); a[2] = tfv(f.y); a[16] = tfv(f.z); a[18] = tfv(f.w);
    }
    __syncthreads();

    // ================= Stage 1 =================
    float acc[4][4][4];
    #pragma unroll
    for (int i = 0; i < 4; i++)
        #pragma unroll
        for (int j = 0; j < 4; j++)
            #pragma unroll
            for (int k = 0; k < 4; k++) acc[i][j][k] = 0.f;

    for (int kc = 0; kc < 32; ++kc) {
        float4 pf[2];
        const bool pre = (kc < 31);
        if (pre) {
            #pragma unroll
            for (int i = 0; i < 2; ++i)
                pf[i] = *reinterpret_cast<const float4*>(
                    x + a_goff[i] + (size_t)(kc + 1) * 1024);
        }

        const float* Ab = AB + (kc & 1) * A_BUF;

        #pragma unroll
        for (int ks2 = 0; ks2 < 2; ++ks2) {
            // consume current B buffer
            uint32_t bb[4][4];
            #pragma unroll
            for (int nf = 0; nf < 4; ++nf) {
                bb[nf][0] = f2tf(Bf[nf].x); bb[nf][1] = f2tf(Bf[nf].y);
                bb[nf][2] = f2tf(Bf[nf].z); bb[nf][3] = f2tf(Bf[nf].w);
            }
            // issue next B block: (kc, 1) or (kc+1 mod 32, 0)
            {
                const float* nw = (ks2 == 0)
                    ? wsp + (kc << 5) + 16
                    : wsp + ((((kc + 1) & 31)) << 5);
                #pragma unroll
                for (int nf = 0; nf < 4; ++nf)
                    Bf[nf] = *reinterpret_cast<const float4*>(nw + nf * 8192);
            }
            #pragma unroll
            for (int s = 0; s < 2; ++s) {
                const int ks = ks2 * 2 + s;
                #pragma unroll
                for (int mf = 0; mf < 4; ++mf) {
                    const float4 fa = *reinterpret_cast<const float4*>(
                        &Ab[(mf * 8 + g) * A_STRIDE + (ks * 4 + tc) * 4]);
                    uint32_t a4[4] = {__float_as_uint(fa.x), __float_as_uint(fa.y),
                                      __float_as_uint(fa.z), __float_as_uint(fa.w)};
                    #pragma unroll
                    for (int nf = 0; nf < 4; ++nf)
                        mma_tf32(acc[mf][nf], a4, bb[nf][2 * s], bb[nf][2 * s + 1]);
                }
            }
        }

        if (pre) {
            float* Aw = AB + ((kc + 1) & 1) * A_BUF;
            #pragma unroll
            for (int i = 0; i < 2; ++i) {
                float* a = Aw + a_soff[i];
                a[0]  = tfv(pf[i].x); a[2]  = tfv(pf[i].y);
                a[16] = tfv(pf[i].z); a[18] = tfv(pf[i].w);
            }
        }
        __syncthreads();
    }

    // preload first stage-2 B block (nc=0, ks2=0) before the MH dump
    #pragma unroll
    for (int nf = 0; nf < 4; ++nf)
        Bf[nf] = *reinterpret_cast<const float4*>(wip + nf * 2048);

    // ---- dump meas to MH at permuted slot positions (STS.128 each) ----
    #pragma unroll
    for (int mf = 0; mf < 4; ++mf) {
        #pragma unroll
        for (int nf = 0; nf < 4; ++nf) {
            int off = (mf * 8 + g) * MH_STRIDE + 64 * warp + 32 * (nf >> 1)
                    + 16 * (tc & 1) + 4 * ((2 * nf + (tc >> 1)) & 3);
            float4 v;
            v.x = tfv(acc[mf][nf][0]);   // (r,   c)
            v.y = tfv(acc[mf][nf][2]);   // (r+8, c)
            v.z = tfv(acc[mf][nf][1]);   // (r,   c+1)
            v.w = tfv(acc[mf][nf][3]);   // (r+8, c+1)
            *reinterpret_cast<float4*>(MH + off) = v;
        }
    }
    __syncthreads();

    // ================= Stage 2 (no barriers, pipelined B) =================
    for (int nc = 0; nc < 4; ++nc) {
        float acc2[4][4][4];
        #pragma unroll
        for (int i = 0; i < 4; i++)
            #pragma unroll
            for (int j = 0; j < 4; j++)
                #pragma unroll
                for (int k = 0; k < 4; k++) acc2[i][j][k] = 0.f;

        const float* wn_ = wip + (size_t)nc * 65536;

        #pragma unroll 2
        for (int ks2 = 0; ks2 < 16; ++ks2) {
            uint32_t bb[4][4];
            #pragma unroll
            for (int nf = 0; nf < 4; ++nf) {
                bb[nf][0] = f2tf(Bf[nf].x); bb[nf][1] = f2tf(Bf[nf].y);
                bb[nf][2] = f2tf(Bf[nf].z); bb[nf][3] = f2tf(Bf[nf].w);
            }
            // issue next B block: (nc, ks2+1), or (nc+1, 0); last: reload (unused)
            {
                const float* nw = (ks2 < 15)
                    ? wn_ + (ks2 + 1) * 16
                    : wip + (size_t)((nc + 1) & 3) * 65536;
                #pragma unroll
                for (int nf = 0; nf < 4; ++nf)
                    Bf[nf] = *reinterpret_cast<const float4*>(nw + nf * 2048);
            }
            #pragma unroll
            for (int s = 0; s < 2; ++s) {
                const int ks = ks2 * 2 + s;
                #pragma unroll
                for (int mf = 0; mf < 4; ++mf) {
                    const float4 fa = *reinterpret_cast<const float4*>(
                        &MH[(mf * 8 + g) * MH_STRIDE + (ks * 4 + tc) * 4]);
                    uint32_t a4[4] = {__float_as_uint(fa.x), __float_as_uint(fa.y),
                                      __float_as_uint(fa.z), __float_as_uint(fa.w)};
                    #pragma unroll
                    for (int nf = 0; nf < 4; ++nf)
                        mma_tf32(acc2[mf][nf], a4, bb[nf][2 * s], bb[nf][2 * s + 1]);
                }
            }
        }

        // epilogue: c = nc*256 + warp*32 + nf*8 + 2tc -> kh = nc*8+warp
        const int kh = nc * 8 + warp;
        #pragma unroll
        for (int mf = 0; mf < 4; ++mf) {
            #pragma unroll
            for (int half = 0; half < 2; ++half) {
                int r   = mf * 16 + g + 8 * half;
                int gp  = p0 + r;
                int b   = gp >> 10;
                int rem = gp & 1023;
                int bh = rem >> 5, bw = rem & 31;
                float* yb = y + ((size_t)b << 20)
                              + (size_t)((bh << 5) + kh) * 1024 + (bw << 5);
                #pragma unroll
                for (int nf = 0; nf < 4; ++nf) {
                    float2 v2;
                    v2.x = acc2[mf][nf][half * 2 + 0];
                    v2.y = acc2[mf][nf][half * 2 + 1];
                    *reinterpret_cast<float2*>(yb + nf * 8 + 2 * tc) = v2;
                }
            }
        }
    }
}

extern "C" void kernel_launch(void* const* d_in, const int* in_sizes, int n_in,
                              void* d_out, int out_size)
{
    const float* x  = (const float*)d_in[0];   // [16,1,1024,1024]
    const float* ws = (const float*)d_in[1];   // [256,1024]
    const float* wi = (const float*)d_in[2];   // [1024,256]
    float* y = (float*)d_out;                  // [16,1,1024,1024]

    cudaFuncSetAttribute(lsm_fused_kernel,
                         cudaFuncAttributeMaxDynamicSharedMemorySize, SMEM_BYTES);
    lsm_fused_kernel<<<N_CTA, N_THREADS, SMEM_BYTES>>>(x, ws, wi, y);
}

// round 16
// speedup vs baseline: 1.6648x; 1.3083x over previous
#include <cuda_runtime.h>
#include <cuda_fp16.h>
#include <cstdint>
#include <cstring>

// LSM_IniReconNet fused two-stage GEMM, fp16 mma.sync m16n8k16 (fp32 accum).
//   stage 1: meas[64,256] = P[64,1024] @ Ws^T   (Ws [256,1024] row-major)
//   stage 2: Y[64,1024]   = meas @ Wi^T         (Wi [1024,256] row-major)
// fp16 keeps tf32's 11-bit significand -> same accuracy class, but halves
// both operand bytes (L1 wavefronts) and tensor cycles. Weights pre-converted
// to __device__ half arrays by a tiny kernel so B fragments are single
// coalesced LDG.64s (the two words ARE b0/b1 under the k-slot permutation
// slot(2tc+e)->4tc+e, slot(2tc+8+e)->4tc+2+e, applied to A and B alike).
// R12's register-level B software pipeline retained. 256 CTAs x 256 threads,
// 2 CTAs/SM.

#define N_THREADS 256
#define N_CTA 256

// smem layout (bytes)
#define MH_STR   1088                 // 68 x 16B units/row; 68 % 8 == 4
#define MH_BYTES (32 * MH_STR)        // 34816
#define A_STR    192                  // 12 x 16B units/row; 12 % 8 == 4
#define A_BUF    (32 * A_STR)         // 6144
#define SMEM_BYTES (MH_BYTES + 2 * A_BUF)   // 47104

__device__ __half g_wsh[256 * 1024];
__device__ __half g_wih[1024 * 256];

__device__ __forceinline__ uint32_t h2u(__half2 h) {
    uint32_t u;
    memcpy(&u, &h, 4);
    return u;
}

__global__ void cvt_weights(const float* __restrict__ ws,
                            const float* __restrict__ wi)
{
    int i = blockIdx.x * blockDim.x + threadIdx.x;    // 0..131071
    const bool first = (i < 65536);
    const float4 f = first ? reinterpret_cast<const float4*>(ws)[i]
                           : reinterpret_cast<const float4*>(wi)[i - 65536];
    __half2 h0 = __floats2half2_rn(f.x, f.y);
    __half2 h1 = __floats2half2_rn(f.z, f.w);
    __half2* dst = first ? reinterpret_cast<__half2*>(g_wsh) + 2 * i
                         : reinterpret_cast<__half2*>(g_wih) + 2 * (i - 65536);
    dst[0] = h0;
    dst[1] = h1;
}

__device__ __forceinline__ void mma_f16(float c[4], const uint32_t a[4],
                                        uint32_t b0, uint32_t b1) {
    asm volatile(
        "mma.sync.aligned.m16n8k16.row.col.f32.f16.f16.f32 "
        "{%0,%1,%2,%3}, {%4,%5,%6,%7}, {%8,%9}, {%0,%1,%2,%3};"
        : "+f"(c[0]), "+f"(c[1]), "+f"(c[2]), "+f"(c[3])
        : "r"(a[0]), "r"(a[1]), "r"(a[2]), "r"(a[3]), "r"(b0), "r"(b1));
}

__global__ void __launch_bounds__(N_THREADS, 2)
lsm_fused_kernel(const float* __restrict__ x, float* __restrict__ y)
{
    extern __shared__ char sm[];
    char* MH = sm;                 // meas, half, 32 grow-rows x 68 units
    char* AB = sm + MH_BYTES;      // 2 x A buffer (half)

    const int tid  = threadIdx.x;
    const int w    = tid >> 5;     // warp owns n-cols [w*32, +32)
    const int lane = tid & 31;
    const int g  = lane >> 2;
    const int tc = lane & 3;
    const int p0 = blockIdx.x * 64;

    // ---- A loader precompute: 2 float4 / thread / kc ----
    // unit layout (16B): [r:(k0,k1) | r:(k2,k3) | r+8:(k0,k1) | r+8:(k2,k3)]
    size_t a_goff[2]; int a_soff[2];
    #pragma unroll
    for (int i = 0; i < 2; ++i) {
        int v = tid + i * 256;
        int p = v >> 3, kq = v & 7;
        int gp = p0 + p;
        int b = gp >> 10, rem = gp & 1023, bh = rem >> 5, bw = rem & 31;
        a_goff[i] = ((size_t)b << 20) + (size_t)(bh << 5) * 1024 + (bw << 5) + (kq << 2);
        int grow = (p >> 4) * 8 + (p & 7);
        a_soff[i] = grow * A_STR + kq * 16 + 8 * ((p >> 3) & 1);
    }

    // half-weight base pointers: row = w*32 + nf*8 + g, inner 4*tc
    const __half* wsp = g_wsh + (size_t)(w * 32 + g) * 1024 + 4 * tc;
    const __half* wip = g_wih + (size_t)(w * 32 + g) * 256 + 4 * tc;

    // ---- prologue: preload B(kc=0,ks=0); stage A(kc=0) ----
    uint2 Bc[4];
    #pragma unroll
    for (int nf = 0; nf < 4; ++nf)
        Bc[nf] = *reinterpret_cast<const uint2*>(wsp + nf * 8192);
    #pragma unroll
    for (int i = 0; i < 2; ++i) {
        const float4 f = *reinterpret_cast<const float4*>(x + a_goff[i]);
        uint2 hv;
        hv.x = h2u(__floats2half2_rn(f.x, f.y));
        hv.y = h2u(__floats2half2_rn(f.z, f.w));
        *reinterpret_cast<uint2*>(AB + a_soff[i]) = hv;
    }
    __syncthreads();

    // ================= Stage 1 =================
    float acc[4][4][4];
    #pragma unroll
    for (int i = 0; i < 4; i++)
        #pragma unroll
        for (int j = 0; j < 4; j++)
            #pragma unroll
            for (int k = 0; k < 4; k++) acc[i][j][k] = 0.f;

    for (int kc = 0; kc < 32; ++kc) {
        float4 pf[2];
        const bool pre = (kc < 31);
        if (pre) {
            #pragma unroll
            for (int i = 0; i < 2; ++i)
                pf[i] = *reinterpret_cast<const float4*>(
                    x + a_goff[i] + (size_t)(kc + 1) * 1024);
        }

        const char* Ab = AB + (kc & 1) * A_BUF;

        #pragma unroll
        for (int ks = 0; ks < 2; ++ks) {     // 2 x k16 per kc
            uint2 bb[4];
            #pragma unroll
            for (int nf = 0; nf < 4; ++nf) bb[nf] = Bc[nf];
            // issue next B block: (kc, 1) or (kc+1 mod 32, 0)
            {
                const __half* nw = (ks == 0)
                    ? wsp + kc * 32 + 16
                    : wsp + ((kc + 1) & 31) * 32;
                #pragma unroll
                for (int nf = 0; nf < 4; ++nf)
                    Bc[nf] = *reinterpret_cast<const uint2*>(nw + nf * 8192);
            }
            #pragma unroll
            for (int mf = 0; mf < 4; ++mf) {
                const uint4 wv = *reinterpret_cast<const uint4*>(
                    Ab + (mf * 8 + g) * A_STR + (ks * 4 + tc) * 16);
                uint32_t a4[4] = {wv.x, wv.z, wv.y, wv.w};
                #pragma unroll
                for (int nf = 0; nf < 4; ++nf)
                    mma_f16(acc[mf][nf], a4, bb[nf].x, bb[nf].y);
            }
        }

        if (pre) {
            char* Aw = AB + ((kc + 1) & 1) * A_BUF;
            #pragma unroll
            for (int i = 0; i < 2; ++i) {
                uint2 hv;
                hv.x = h2u(__floats2half2_rn(pf[i].x, pf[i].y));
                hv.y = h2u(__floats2half2_rn(pf[i].z, pf[i].w));
                *reinterpret_cast<uint2*>(Aw + a_soff[i]) = hv;
            }
        }
        __syncthreads();
    }

    // preload first stage-2 B block (nc=0, ks16=0)
    #pragma unroll
    for (int nf = 0; nf < 4; ++nf)
        Bc[nf] = *reinterpret_cast<const uint2*>(wip + nf * 2048);

    // ---- dump meas to MH (half), at permuted slot positions ----
    // s = 32w + 8nf + 2tc (+e):  C = w*2 + (nf>>1), tc2 = (nf&1)*2 + (tc>>1)
    #pragma unroll
    for (int mf = 0; mf < 4; ++mf) {
        #pragma unroll
        for (int nf = 0; nf < 4; ++nf) {
            int ub = (mf * 8 + g) * MH_STR
                   + ((w * 2 + (nf >> 1)) * 4 + (nf & 1) * 2 + (tc >> 1)) * 16
                   + 4 * (tc & 1);
            *reinterpret_cast<__half2*>(MH + ub) =
                __floats2half2_rn(acc[mf][nf][0], acc[mf][nf][1]);   // r
            *reinterpret_cast<__half2*>(MH + ub + 8) =
                __floats2half2_rn(acc[mf][nf][2], acc[mf][nf][3]);   // r+8
        }
    }
    __syncthreads();

    // ================= Stage 2 (no barriers, pipelined B) =================
    for (int nc = 0; nc < 4; ++nc) {
        float acc2[4][4][4];
        #pragma unroll
        for (int i = 0; i < 4; i++)
            #pragma unroll
            for (int j = 0; j < 4; j++)
                #pragma unroll
                for (int k = 0; k < 4; k++) acc2[i][j][k] = 0.f;

        const __half* wn_ = wip + (size_t)nc * 65536;

        #pragma unroll 2
        for (int ks = 0; ks < 16; ++ks) {    // 16 x k16 over s=256
            uint2 bb[4];
            #pragma unroll
            for (int nf = 0; nf < 4; ++nf) bb[nf] = Bc[nf];
            {
                const __half* nw = (ks < 15)
                    ? wn_ + (ks + 1) * 16
                    : wip + (size_t)((nc + 1) & 3) * 65536;
                #pragma unroll
                for (int nf = 0; nf < 4; ++nf)
                    Bc[nf] = *reinterpret_cast<const uint2*>(nw + nf * 2048);
            }
            #pragma unroll
            for (int mf = 0; mf < 4; ++mf) {
                const uint4 wv = *reinterpret_cast<const uint4*>(
                    MH + (mf * 8 + g) * MH_STR + (ks * 4 + tc) * 16);
                uint32_t a4[4] = {wv.x, wv.z, wv.y, wv.w};
                #pragma unroll
                for (int nf = 0; nf < 4; ++nf)
                    mma_f16(acc2[mf][nf], a4, bb[nf].x, bb[nf].y);
            }
        }

        // epilogue: c = nc*256 + w*32 + nf*8 + 2tc -> kh = nc*8 + w
        const int kh = nc * 8 + w;
        #pragma unroll
        for (int mf = 0; mf < 4; ++mf) {
            #pragma unroll
            for (int half_ = 0; half_ < 2; ++half_) {
                int r   = mf * 16 + g + 8 * half_;
                int gp  = p0 + r;
                int b   = gp >> 10;
                int rem = gp & 1023;
                int bh = rem >> 5, bw = rem & 31;
                float* yb = y + ((size_t)b << 20)
                              + (size_t)((bh << 5) + kh) * 1024 + (bw << 5);
                #pragma unroll
                for (int nf = 0; nf < 4; ++nf) {
                    float2 v2;
                    v2.x = acc2[mf][nf][half_ * 2 + 0];
                    v2.y = acc2[mf][nf][half_ * 2 + 1];
                    *reinterpret_cast<float2*>(yb + nf * 8 + 2 * tc) = v2;
                }
            }
        }
    }
}

extern "C" void kernel_launch(void* const* d_in, const int* in_sizes, int n_in,
                              void* d_out, int out_size)
{
    const float* x  = (const float*)d_in[0];   // [16,1,1024,1024]
    const float* ws = (const float*)d_in[1];   // [256,1024]
    const float* wi = (const float*)d_in[2];   // [1024,256]
    float* y = (float*)d_out;                  // [16,1,1024,1024]

    cvt_weights<<<512, 256>>>(ws, wi);
    cudaFuncSetAttribute(lsm_fused_kernel,
                         cudaFuncAttributeMaxDynamicSharedMemorySize, SMEM_BYTES);
    lsm_fused_kernel<<<N_CTA, N_THREADS, SMEM_BYTES>>>(x, y);
}